// round 13
// baseline (speedup 1.0000x reference)
#include <cuda_runtime.h>
#include <cuda_bf16.h>
#include <math.h>
#include <stdint.h>

#define NL 12
#define NH 16
#define NC 1024
#define NT 512
#define NB 4
#define HDIM 64
#define NF 4096
#define NV 32000
#define MROWS (NB*NT)   // 2048
#define C3 (3*NC)       // 3072
#define LN_EPS 1e-5f

typedef __nv_bfloat16 bf16;
typedef __nv_bfloat162 bf162;

// ---------------- static scratch ----------------
__device__ float g_x   [MROWS*NC];
__device__ float g_qkv [MROWS*C3];
__device__ bf16  g_xn_h[MROWS*NC];
__device__ bf16  g_xn_l[MROWS*NC];
__device__ bf16  g_y_h [MROWS*NC];
__device__ bf16  g_y_l [MROWS*NC];
__device__ bf16  g_h_h [MROWS*NF];
__device__ bf16  g_h_l [MROWS*NF];

// split weights, K-major W[K,N] (as in reference)
__device__ bf16 g_wqkv_h[(long)NL*NC*C3];
__device__ bf16 g_wqkv_l[(long)NL*NC*C3];
__device__ bf16 g_wo_h  [(long)NL*NC*NC];
__device__ bf16 g_wo_l  [(long)NL*NC*NC];
__device__ bf16 g_w1_h  [(long)NL*NC*NF];
__device__ bf16 g_w1_l  [(long)NL*NC*NF];
__device__ bf16 g_w2_h  [(long)NL*NF*NC];
__device__ bf16 g_w2_l  [(long)NL*NF*NC];
__device__ bf16 g_lm_h  [(long)NC*NV];
__device__ bf16 g_lm_l  [(long)NC*NV];

__device__ __forceinline__ void split2(float v, bf16& h, bf16& l) {
    h = __float2bfloat16(v);
    l = __float2bfloat16(v - __bfloat162float(h));
}

// ---------------- conversion kernels ----------------
__global__ void split4_kernel(const float* __restrict__ i0, bf16* __restrict__ h0, bf16* __restrict__ l0, long n0,
                              const float* __restrict__ i1, bf16* __restrict__ h1, bf16* __restrict__ l1, long n1,
                              const float* __restrict__ i2, bf16* __restrict__ h2, bf16* __restrict__ l2, long n2,
                              const float* __restrict__ i3, bf16* __restrict__ h3, bf16* __restrict__ l3, long n3) {
    long total = n0 + n1 + n2 + n3;
    for (long i = (long)blockIdx.x * blockDim.x + threadIdx.x; i < total;
         i += (long)gridDim.x * blockDim.x) {
        const float* in; bf16 *oh, *ol; long j = i;
        if (j < n0)                { in = i0; oh = h0; ol = l0; }
        else if ((j -= n0) < n1)   { in = i1; oh = h1; ol = l1; }
        else if ((j -= n1) < n2)   { in = i2; oh = h2; ol = l2; }
        else { j -= n2;              in = i3; oh = h3; ol = l3; }
        float v = in[j];
        bf16 h, l; split2(v, h, l);
        oh[j] = h; ol[j] = l;
    }
}

__global__ void pack_qkv_kernel(const float* __restrict__ wq,
                                const float* __restrict__ wk,
                                const float* __restrict__ wv,
                                bf16* __restrict__ oh, bf16* __restrict__ ol, long n) {
    for (long i = (long)blockIdx.x * blockDim.x + threadIdx.x; i < n;
         i += (long)gridDim.x * blockDim.x) {
        long lk = i / C3;        // l*NC + k
        int  j  = (int)(i % C3);
        int sel = j >> 10, jj = j & 1023;
        const float* src = (sel == 0) ? wq : (sel == 1) ? wk : wv;
        float v = src[lk * NC + jj];
        bf16 h, l; split2(v, h, l);
        oh[i] = h; ol[i] = l;
    }
}

// ---------------- embedding ----------------
__global__ void embed_kernel(const int* __restrict__ idx,
                             const float* __restrict__ tok,
                             const float* __restrict__ pos) {
    int row = blockIdx.x, t = row % NT;
    int tk = idx[row];
    const float4* tr = (const float4*)(tok + (long)tk * NC);
    const float4* pr = (const float4*)(pos + (long)t  * NC);
    float4* xr = (float4*)(g_x + (long)row * NC);
    for (int c = threadIdx.x; c < NC / 4; c += blockDim.x) {
        float4 a = tr[c], b = pr[c];
        a.x += b.x; a.y += b.y; a.z += b.z; a.w += b.w;
        xr[c] = a;
    }
}

// ---------------- layernorm + split (256 thr/row) ----------------
__global__ __launch_bounds__(256)
void ln_split_kernel(const float* __restrict__ x,
                     const float* __restrict__ gg,
                     const float* __restrict__ bb,
                     bf16* __restrict__ oh, bf16* __restrict__ ol) {
    __shared__ float rs[8], rs2[8];
    const int row = blockIdx.x, tid = threadIdx.x;
    const float4* xr = (const float4*)(x + (long)row * NC);
    float4 v = xr[tid];
    float s  = v.x + v.y + v.z + v.w;
    float s2 = v.x*v.x + v.y*v.y + v.z*v.z + v.w*v.w;
    #pragma unroll
    for (int off = 16; off > 0; off >>= 1) {
        s  += __shfl_xor_sync(0xffffffff, s,  off);
        s2 += __shfl_xor_sync(0xffffffff, s2, off);
    }
    if ((tid & 31) == 0) { rs[tid >> 5] = s; rs2[tid >> 5] = s2; }
    __syncthreads();
    if (tid < 8) {
        s = rs[tid]; s2 = rs2[tid];
        #pragma unroll
        for (int off = 4; off > 0; off >>= 1) {
            s  += __shfl_xor_sync(0xff, s,  off);
            s2 += __shfl_xor_sync(0xff, s2, off);
        }
        if (tid == 0) { rs[0] = s; rs2[0] = s2; }
    }
    __syncthreads();
    float mean = rs[0] * (1.0f / NC);
    float var  = rs2[0] * (1.0f / NC) - mean * mean;
    float rstd = rsqrtf(var + LN_EPS);
    const float4* g4 = (const float4*)gg;
    const float4* b4 = (const float4*)bb;
    float4 g = g4[tid], bv = b4[tid];
    float o0 = (v.x - mean) * rstd * g.x + bv.x;
    float o1 = (v.y - mean) * rstd * g.y + bv.y;
    float o2 = (v.z - mean) * rstd * g.z + bv.z;
    float o3 = (v.w - mean) * rstd * g.w + bv.w;
    bf16 h0,l0,h1,l1,h2,l2,h3,l3;
    split2(o0,h0,l0); split2(o1,h1,l1); split2(o2,h2,l2); split2(o3,h3,l3);
    bf162* oh2 = (bf162*)(oh + (long)row * NC);
    bf162* ol2 = (bf162*)(ol + (long)row * NC);
    oh2[tid*2]   = bf162(h0, h1);
    oh2[tid*2+1] = bf162(h2, h3);
    ol2[tid*2]   = bf162(l0, l1);
    ol2[tid*2+1] = bf162(l2, l3);
}

// ---------------- mma.sync helpers ----------------
__device__ __forceinline__ void ldsm_x4(uint32_t addr, uint32_t& r0, uint32_t& r1,
                                        uint32_t& r2, uint32_t& r3) {
    asm volatile("ldmatrix.sync.aligned.m8n8.x4.shared.b16 {%0,%1,%2,%3},[%4];"
                 : "=r"(r0), "=r"(r1), "=r"(r2), "=r"(r3) : "r"(addr));
}
__device__ __forceinline__ void ldsm_x4_t(uint32_t addr, uint32_t& r0, uint32_t& r1,
                                          uint32_t& r2, uint32_t& r3) {
    asm volatile("ldmatrix.sync.aligned.m8n8.x4.trans.shared.b16 {%0,%1,%2,%3},[%4];"
                 : "=r"(r0), "=r"(r1), "=r"(r2), "=r"(r3) : "r"(addr));
}
__device__ __forceinline__ void mma_bf16(float* c, const uint32_t* a, const uint32_t* b) {
    asm volatile(
        "mma.sync.aligned.m16n8k16.row.col.f32.bf16.bf16.f32 "
        "{%0,%1,%2,%3},{%4,%5,%6,%7},{%8,%9},{%0,%1,%2,%3};"
        : "+f"(c[0]), "+f"(c[1]), "+f"(c[2]), "+f"(c[3])
        : "r"(a[0]), "r"(a[1]), "r"(a[2]), "r"(a[3]), "r"(b[0]), "r"(b[1]));
}
__device__ __forceinline__ void cpa16(uint32_t s, const void* g) {
    asm volatile("cp.async.cg.shared.global [%0],[%1],16;" :: "r"(s), "l"(g));
}

// ---------------- split-bf16 tensor-core GEMM (R7 2-stage pipeline, BM templated) -------
// C = Ah@Bh + Al@Bh + Ah@Bl, fp32 accum. IM=2 -> BM=128, IM=1 -> BM=64. BN=128, BK=32.
// stage = A(hi+lo) 2*BM*64B + B(hi+lo) 16KB; 2 stages.
// EPI: 0 = fp32 out; 1 = +bias +res fp32 out; 2 = +bias relu split bf16 out.
#define SMEM_G128 65536
#define SMEM_G64  49152

template<int EPI, int IM>
__global__ __launch_bounds__(256, 2)
void mma_gemm(int M, int N, int K,
              const bf16* __restrict__ Ah, const bf16* __restrict__ Al,
              const bf16* __restrict__ Bh, const bf16* __restrict__ Bl,
              const float* __restrict__ bias, const float* __restrict__ res,
              float* __restrict__ Cf, bf16* __restrict__ Ch, bf16* __restrict__ Cl) {
    const int BM = 64 * IM;
    const int ABYTES = BM * 64;            // one A operand (hi or lo) per stage
    const int STG = 2 * ABYTES + 16384;    // stage bytes
    extern __shared__ char smem[];
    const uint32_t sbase0 = (uint32_t)__cvta_generic_to_shared(smem);
    const int tid  = threadIdx.x;
    const int lane = tid & 31, warp = tid >> 5;
    const int wm = warp >> 1, wn = warp & 1;        // 4 x 2 warps
    const int m0 = blockIdx.y * BM, n0 = blockIdx.x * 128;
    const int r8 = lane & 7, grp = lane >> 3;
    const int g = lane >> 2, t4 = lane & 3;

    float acc[IM][8][4];
    #pragma unroll
    for (int i = 0; i < IM; i++)
        #pragma unroll
        for (int j = 0; j < 8; j++)
            #pragma unroll
            for (int r = 0; r < 4; r++) acc[i][j][r] = 0.f;

    const int T = K >> 5;

    auto load_stage = [&](int stage, int k0) {
        uint32_t sb = sbase0 + stage * STG;
        #pragma unroll
        for (int it = 0; it < IM; it++) {
            int c = it * 256 + tid;          // 0..BM*4-1
            int r = c >> 2, cc = c & 3;      // 4 x 16B chunks per 64B row
            uint32_t so = r * 64 + ((cc ^ ((r >> 1) & 3)) << 4);
            size_t ga = (size_t)(m0 + r) * K + k0 + (cc << 3);
            cpa16(sb +          so, Ah + ga);
            cpa16(sb + ABYTES + so, Al + ga);
        }
        #pragma unroll
        for (int it = 0; it < 2; it++) {
            int c = it * 256 + tid;          // 0..511
            int k = c >> 4, nc = c & 15;     // 16 x 16B chunks per 256B row
            uint32_t so = k * 256 + ((nc ^ (k & 7)) << 4);
            size_t ga = (size_t)(k0 + k) * N + n0 + (nc << 3);
            cpa16(sb + 2*ABYTES +        so, Bh + ga);
            cpa16(sb + 2*ABYTES + 8192 + so, Bl + ga);
        }
    };

    load_stage(0, 0);
    asm volatile("cp.async.commit_group;");

    for (int t = 0; t < T; t++) {
        if (t + 1 < T) {
            load_stage((t + 1) & 1, (t + 1) << 5);
            asm volatile("cp.async.commit_group;");
            asm volatile("cp.async.wait_group 1;");
        } else {
            asm volatile("cp.async.wait_group 0;");
        }
        __syncthreads();

        uint32_t sA  = sbase0 + (t & 1) * STG;
        uint32_t sAl = sA + ABYTES;
        uint32_t sB  = sA + 2*ABYTES;
        uint32_t sBl = sB + 8192;

        #pragma unroll
        for (int kt = 0; kt < 2; kt++) {
            uint32_t ah[IM][4], al_[IM][4];
            #pragma unroll
            for (int i = 0; i < IM; i++) {
                int row = wm * (16*IM) + i * 16 + r8 + ((grp & 1) << 3);
                int kc  = kt * 2 + (grp >> 1);
                uint32_t off = row * 64 + ((kc ^ ((row >> 1) & 3)) << 4);
                ldsm_x4(sA  + off, ah[i][0],  ah[i][1],  ah[i][2],  ah[i][3]);
                ldsm_x4(sAl + off, al_[i][0], al_[i][1], al_[i][2], al_[i][3]);
            }
            #pragma unroll
            for (int half = 0; half < 2; half++) {
                uint32_t bh[4][2], bl_[4][2];
                #pragma unroll
                for (int j4 = 0; j4 < 2; j4++) {
                    int k = kt * 16 + r8 + ((grp & 1) << 3);
                    int nch = wn * 8 + (half * 2 + j4) * 2 + (grp >> 1);
                    uint32_t off = k * 256 + ((nch ^ (k & 7)) << 4);
                    ldsm_x4_t(sB  + off, bh[2*j4][0],  bh[2*j4][1],  bh[2*j4+1][0],  bh[2*j4+1][1]);
                    ldsm_x4_t(sBl + off, bl_[2*j4][0], bl_[2*j4][1], bl_[2*j4+1][0], bl_[2*j4+1][1]);
                }
                #pragma unroll
                for (int i = 0; i < IM; i++)
                    #pragma unroll
                    for (int jl = 0; jl < 4; jl++) {
                        float* a = acc[i][half * 4 + jl];
                        mma_bf16(a, ah[i],  bh[jl]);
                        mma_bf16(a, al_[i], bh[jl]);
                        mma_bf16(a, ah[i],  bl_[jl]);
                    }
            }
        }
        __syncthreads();
    }

    #pragma unroll
    for (int i = 0; i < IM; i++) {
        int ra = m0 + wm * (16*IM) + i * 16 + g;
        int rb = ra + 8;
        #pragma unroll
        for (int j = 0; j < 8; j++) {
            int c = n0 + wn * 64 + j * 8 + t4 * 2;
            float v0 = acc[i][j][0], v1 = acc[i][j][1];
            float v2 = acc[i][j][2], v3 = acc[i][j][3];
            if (EPI >= 1) {
                float b0 = bias[c], b1 = bias[c + 1];
                v0 += b0; v1 += b1; v2 += b0; v3 += b1;
            }
            if (EPI == 1) {
                const float2 ra2 = *(const float2*)(res + (size_t)ra * N + c);
                const float2 rb2 = *(const float2*)(res + (size_t)rb * N + c);
                v0 += ra2.x; v1 += ra2.y; v2 += rb2.x; v3 += rb2.y;
            }
            if (EPI <= 1) {
                *(float2*)(Cf + (size_t)ra * N + c) = make_float2(v0, v1);
                *(float2*)(Cf + (size_t)rb * N + c) = make_float2(v2, v3);
            } else {
                v0 = fmaxf(v0, 0.f); v1 = fmaxf(v1, 0.f);
                v2 = fmaxf(v2, 0.f); v3 = fmaxf(v3, 0.f);
                bf16 h0,l0,h1,l1,h2,l2,h3,l3;
                split2(v0,h0,l0); split2(v1,h1,l1);
                split2(v2,h2,l2); split2(v3,h3,l3);
                *(bf162*)(Ch + (size_t)ra * N + c) = bf162(h0, h1);
                *(bf162*)(Ch + (size_t)rb * N + c) = bf162(h2, h3);
                *(bf162*)(Cl + (size_t)ra * N + c) = bf162(l0, l1);
                *(bf162*)(Cl + (size_t)rb * N + c) = bf162(l2, l3);
            }
        }
    }
}

// ---------------- flash attention (fp32 compute, split-bf16 output) ----------------
#define AQ_PAD 65
#define AV_PAD 68
#define A_QS 0
#define A_KS (64*AQ_PAD)
#define A_VS (A_KS + 64*AQ_PAD)
#define A_PS (A_VS + 64*AV_PAD)
#define A_ST (A_PS + 64*AQ_PAD)
#define SMEM_ATTN ((A_ST + 3*64) * 4)

__global__ __launch_bounds__(256, 2)
void attn_kernel(const float* __restrict__ QKV,
                 bf16* __restrict__ Yh, bf16* __restrict__ Yl) {
    extern __shared__ float sm[];
    float* Qs = sm + A_QS;          // [d][q]
    float* Ks = sm + A_KS;          // [d][s]
    float* Vs = sm + A_VS;          // [s][d]
    float* Ps = sm + A_PS;          // [q][s]
    float* smM = sm + A_ST;
    float* smL = smM + 64;
    float* smC = smL + 64;

    const int qt = (int)(gridDim.x - 1 - blockIdx.x);   // heavy tiles first
    const int h = blockIdx.y, b = blockIdx.z;
    const int tid = threadIdx.x;
    const int qx = tid >> 4, kx = tid & 15;
    const long baseQ = (long)(b * NT) * C3 + h * HDIM;
    const long baseK = baseQ + NC;
    const long baseV = baseQ + 2 * NC;
    const int q0 = qt * 64;

    #pragma unroll
    for (int it = 0; it < 4; it++) {
        int i = it * 256 + tid;
        int r = i >> 4, dc = (i & 15) * 4;
        float4 v = *(const float4*)&QKV[baseQ + (long)(q0 + r) * C3 + dc];
        Qs[(dc+0)*AQ_PAD + r] = v.x; Qs[(dc+1)*AQ_PAD + r] = v.y;
        Qs[(dc+2)*AQ_PAD + r] = v.z; Qs[(dc+3)*AQ_PAD + r] = v.w;
    }
    if (tid < 64) { smM[tid] = -1e30f; smL[tid] = 0.f; }

    float O[4][4];
    #pragma unroll
    for (int i = 0; i < 4; i++)
        #pragma unroll
        for (int j = 0; j < 4; j++) O[i][j] = 0.f;
    __syncthreads();

    for (int jt = 0; jt <= qt; jt++) {
        #pragma unroll
        for (int it = 0; it < 4; it++) {
            int i = it * 256 + tid;
            int r = i >> 4, dc = (i & 15) * 4;
            float4 v = *(const float4*)&QKV[baseK + (long)(jt * 64 + r) * C3 + dc];
            Ks[(dc+0)*AQ_PAD + r] = v.x; Ks[(dc+1)*AQ_PAD + r] = v.y;
            Ks[(dc+2)*AQ_PAD + r] = v.z; Ks[(dc+3)*AQ_PAD + r] = v.w;
            float4 w = *(const float4*)&QKV[baseV + (long)(jt * 64 + r) * C3 + dc];
            *(float4*)&Vs[r * AV_PAD + dc] = w;
        }
        __syncthreads();

        float S[4][4];
        #pragma unroll
        for (int i = 0; i < 4; i++)
            #pragma unroll
            for (int j = 0; j < 4; j++) S[i][j] = 0.f;
        #pragma unroll 4
        for (int d = 0; d < 64; d++) {
            float qm[4], kn[4];
            #pragma unroll
            for (int i = 0; i < 4; i++) qm[i] = Qs[d*AQ_PAD + qx*4 + i];
            #pragma unroll
            for (int j = 0; j < 4; j++) kn[j] = Ks[d*AQ_PAD + kx*4 + j];
            #pragma unroll
            for (int i = 0; i < 4; i++)
                #pragma unroll
                for (int j = 0; j < 4; j++) S[i][j] += qm[i] * kn[j];
        }
        const bool diag = (jt == qt);
        #pragma unroll
        for (int i = 0; i < 4; i++)
            #pragma unroll
            for (int j = 0; j < 4; j++) {
                float s = S[i][j] * 0.125f;
                if (diag && (jt*64 + kx*4 + j > q0 + qx*4 + i)) s = -1e30f;
                Ps[(qx*4+i)*AQ_PAD + kx*4 + j] = s;
            }
        __syncthreads();

        if (tid < 64) {
            float mo = smM[tid], rmax = mo;
            #pragma unroll 8
            for (int s = 0; s < 64; s++) rmax = fmaxf(rmax, Ps[tid*AQ_PAD + s]);
            float c = __expf(mo - rmax);
            float rsum = 0.f;
            #pragma unroll 8
            for (int s = 0; s < 64; s++) {
                float p = __expf(Ps[tid*AQ_PAD + s] - rmax);
                Ps[tid*AQ_PAD + s] = p;
                rsum += p;
            }
            smL[tid] = smL[tid] * c + rsum;
            smM[tid] = rmax;
            smC[tid] = c;
        }
        __syncthreads();

        float cq[4];
        #pragma unroll
        for (int i = 0; i < 4; i++) cq[i] = smC[qx*4 + i];
        #pragma unroll
        for (int i = 0; i < 4; i++)
            #pragma unroll
            for (int j = 0; j < 4; j++) O[i][j] *= cq[i];
        #pragma unroll 4
        for (int s = 0; s < 64; s++) {
            float pv[4], vv[4];
            #pragma unroll
            for (int i = 0; i < 4; i++) pv[i] = Ps[(qx*4+i)*AQ_PAD + s];
            #pragma unroll
            for (int j = 0; j < 4; j++) vv[j] = Vs[s*AV_PAD + kx*4 + j];
            #pragma unroll
            for (int i = 0; i < 4; i++)
                #pragma unroll
                for (int j = 0; j < 4; j++) O[i][j] += pv[i] * vv[j];
        }
        __syncthreads();
    }

    #pragma unroll
    for (int i = 0; i < 4; i++) {
        float inv = 1.0f / smL[qx*4 + i];
        long row = (long)(b * NT + q0 + qx*4 + i);
        long o = row * NC + h * HDIM + kx*4;
        #pragma unroll
        for (int j = 0; j < 4; j += 2) {
            float v0 = O[i][j] * inv, v1 = O[i][j+1] * inv;
            bf16 h0, l0, h1, l1;
            split2(v0, h0, l0); split2(v1, h1, l1);
            *(bf162*)(Yh + o + j) = bf162(h0, h1);
            *(bf162*)(Yl + o + j) = bf162(l0, l1);
        }
    }
}

// ---------------- host driver ----------------
extern "C" void kernel_launch(void* const* d_in, const int* in_sizes, int n_in,
                              void* d_out, int out_size) {
    const int*   idx  = (const int*)  d_in[0];
    const float* tok  = (const float*)d_in[1];
    const float* pos  = (const float*)d_in[2];
    const float* wq   = (const float*)d_in[3];
    const float* wk   = (const float*)d_in[4];
    const float* wv   = (const float*)d_in[5];
    const float* wo   = (const float*)d_in[6];
    const float* bo   = (const float*)d_in[7];
    const float* ln1g = (const float*)d_in[8];
    const float* ln1b = (const float*)d_in[9];
    const float* ln2g = (const float*)d_in[10];
    const float* ln2b = (const float*)d_in[11];
    const float* w1   = (const float*)d_in[12];
    const float* b1   = (const float*)d_in[13];
    const float* w2   = (const float*)d_in[14];
    const float* b2   = (const float*)d_in[15];
    const float* lnfg = (const float*)d_in[16];
    const float* lnfb = (const float*)d_in[17];
    const float* wlm  = (const float*)d_in[18];
    float* out = (float*)d_out;

    static bool attr_done = false;
    if (!attr_done) {
        cudaFuncSetAttribute(mma_gemm<0,2>, cudaFuncAttributeMaxDynamicSharedMemorySize, SMEM_G128);
        cudaFuncSetAttribute(mma_gemm<1,1>, cudaFuncAttributeMaxDynamicSharedMemorySize, SMEM_G64);
        cudaFuncSetAttribute(mma_gemm<2,2>, cudaFuncAttributeMaxDynamicSharedMemorySize, SMEM_G128);
        cudaFuncSetAttribute(attn_kernel, cudaFuncAttributeMaxDynamicSharedMemorySize, SMEM_ATTN);
        attr_done = true;
    }

    float *x, *qkv;
    bf16 *xnh, *xnl, *yh, *yl, *hh, *hl;
    bf16 *wqkvh, *wqkvl, *woh, *wol, *w1h, *w1l, *w2h, *w2l, *lmh, *lml;
    cudaGetSymbolAddress((void**)&x,     g_x);
    cudaGetSymbolAddress((void**)&qkv,   g_qkv);
    cudaGetSymbolAddress((void**)&xnh,   g_xn_h);
    cudaGetSymbolAddress((void**)&xnl,   g_xn_l);
    cudaGetSymbolAddress((void**)&yh,    g_y_h);
    cudaGetSymbolAddress((void**)&yl,    g_y_l);
    cudaGetSymbolAddress((void**)&hh,    g_h_h);
    cudaGetSymbolAddress((void**)&hl,    g_h_l);
    cudaGetSymbolAddress((void**)&wqkvh, g_wqkv_h);
    cudaGetSymbolAddress((void**)&wqkvl, g_wqkv_l);
    cudaGetSymbolAddress((void**)&woh,   g_wo_h);
    cudaGetSymbolAddress((void**)&wol,   g_wo_l);
    cudaGetSymbolAddress((void**)&w1h,   g_w1_h);
    cudaGetSymbolAddress((void**)&w1l,   g_w1_l);
    cudaGetSymbolAddress((void**)&w2h,   g_w2_h);
    cudaGetSymbolAddress((void**)&w2l,   g_w2_l);
    cudaGetSymbolAddress((void**)&lmh,   g_lm_h);
    cudaGetSymbolAddress((void**)&lml,   g_lm_l);

    pack_qkv_kernel<<<4096, 256>>>(wq, wk, wv, wqkvh, wqkvl, (long)NL*NC*C3);
    split4_kernel<<<8192, 256>>>(wo,  woh, wol, (long)NL*NC*NC,
                                 w1,  w1h, w1l, (long)NL*NC*NF,
                                 w2,  w2h, w2l, (long)NL*NF*NC,
                                 wlm, lmh, lml, (long)NC*NV);
    embed_kernel<<<MROWS, 256>>>(idx, tok, pos);

    for (int l = 0; l < NL; l++) {
        const long oQ = (long)l * NC * C3;
        const long oO = (long)l * NC * NC;
        const long o1 = (long)l * NC * NF;
        const long o2 = (long)l * NF * NC;

        ln_split_kernel<<<MROWS, 256>>>(x, ln1g + l*NC, ln1b + l*NC, xnh, xnl);
        mma_gemm<0,2><<<dim3(C3/128, MROWS/128), 256, SMEM_G128>>>(
            MROWS, C3, NC, xnh, xnl, wqkvh + oQ, wqkvl + oQ,
            nullptr, nullptr, qkv, nullptr, nullptr);
        attn_kernel<<<dim3(NT/64, NH, NB), 256, SMEM_ATTN>>>(qkv, yh, yl);
        mma_gemm<1,1><<<dim3(NC/128, MROWS/64), 256, SMEM_G64>>>(
            MROWS, NC, NC, yh, yl, woh + oO, wol + oO,
            bo + l*NC, x, x, nullptr, nullptr);
        ln_split_kernel<<<MROWS, 256>>>(x, ln2g + l*NC, ln2b + l*NC, xnh, xnl);
        mma_gemm<2,2><<<dim3(NF/128, MROWS/128), 256, SMEM_G128>>>(
            MROWS, NF, NC, xnh, xnl, w1h + o1, w1l + o1,
            b1 + l*NF, nullptr, nullptr, hh, hl);
        mma_gemm<1,1><<<dim3(NC/128, MROWS/64), 256, SMEM_G64>>>(
            MROWS, NC, NF, hh, hl, w2h + o2, w2l + o2,
            b2 + l*NC, x, x, nullptr, nullptr);
    }

    ln_split_kernel<<<MROWS, 256>>>(x, lnfg, lnfb, xnh, xnl);
    mma_gemm<0,2><<<dim3(NV/128, MROWS/128), 256, SMEM_G128>>>(
        MROWS, NV, NC, xnh, xnl, lmh, lml,
        nullptr, nullptr, out, nullptr, nullptr);
}

// round 14
// speedup vs baseline: 1.2387x; 1.2387x over previous
#include <cuda_runtime.h>
#include <cuda_fp16.h>
#include <math.h>
#include <stdint.h>

#define NL 12
#define NH 16
#define NC 1024
#define NT 512
#define NB 4
#define HDIM 64
#define NF 4096
#define NV 32000
#define MROWS (NB*NT)   // 2048
#define C3 (3*NC)       // 3072
#define LN_EPS 1e-5f

typedef __half fp16;

// ---------------- static scratch ----------------
__device__ float g_x   [MROWS*NC];
__device__ float g_qkv [MROWS*C3];
__device__ fp16  g_xn_h[MROWS*NC];
__device__ fp16  g_xn_l[MROWS*NC];
__device__ fp16  g_y_h [MROWS*NC];
__device__ fp16  g_y_l [MROWS*NC];
__device__ fp16  g_h_h [MROWS*NF];
__device__ fp16  g_h_l [MROWS*NF];

// weights, K-major W[K,N], single fp16
__device__ fp16 g_wqkv[(long)NL*NC*C3];
__device__ fp16 g_wo  [(long)NL*NC*NC];
__device__ fp16 g_w1  [(long)NL*NC*NF];
__device__ fp16 g_w2  [(long)NL*NF*NC];
__device__ fp16 g_lm  [(long)NC*NV];

__device__ __forceinline__ void split2h(float v, fp16& h, fp16& l) {
    h = __float2half_rn(v);
    l = __float2half_rn(v - __half2float(h));
}
__device__ __forceinline__ uint32_t pack2(fp16 a, fp16 b) {
    __half2 p = __halves2half2(a, b);
    return *(uint32_t*)&p;
}

// ---------------- conversion kernels ----------------
// 4 independent fp32->fp16 conversions fused
__global__ void conv4_kernel(const float* __restrict__ i0, fp16* __restrict__ o0, long n0,
                             const float* __restrict__ i1, fp16* __restrict__ o1, long n1,
                             const float* __restrict__ i2, fp16* __restrict__ o2, long n2,
                             const float* __restrict__ i3, fp16* __restrict__ o3, long n3) {
    long total = n0 + n1 + n2 + n3;
    for (long i = (long)blockIdx.x * blockDim.x + threadIdx.x; i < total;
         i += (long)gridDim.x * blockDim.x) {
        const float* in; fp16* o; long j = i;
        if (j < n0)                { in = i0; o = o0; }
        else if ((j -= n0) < n1)   { in = i1; o = o1; }
        else if ((j -= n1) < n2)   { in = i2; o = o2; }
        else { j -= n2;              in = i3; o = o3; }
        o[j] = __float2half_rn(in[j]);
    }
}

__global__ void pack_qkv_kernel(const float* __restrict__ wq,
                                const float* __restrict__ wk,
                                const float* __restrict__ wv,
                                fp16* __restrict__ o, long n) {
    for (long i = (long)blockIdx.x * blockDim.x + threadIdx.x; i < n;
         i += (long)gridDim.x * blockDim.x) {
        long lk = i / C3;        // l*NC + k
        int  j  = (int)(i % C3);
        int sel = j >> 10, jj = j & 1023;
        const float* src = (sel == 0) ? wq : (sel == 1) ? wk : wv;
        o[i] = __float2half_rn(src[lk * NC + jj]);
    }
}

// ---------------- embedding ----------------
__global__ void embed_kernel(const int* __restrict__ idx,
                             const float* __restrict__ tok,
                             const float* __restrict__ pos) {
    int row = blockIdx.x, t = row % NT;
    int tk = idx[row];
    const float4* tr = (const float4*)(tok + (long)tk * NC);
    const float4* pr = (const float4*)(pos + (long)t  * NC);
    float4* xr = (float4*)(g_x + (long)row * NC);
    for (int c = threadIdx.x; c < NC / 4; c += blockDim.x) {
        float4 a = tr[c], b = pr[c];
        a.x += b.x; a.y += b.y; a.z += b.z; a.w += b.w;
        xr[c] = a;
    }
}

// ---------------- layernorm + fp16 split (256 thr/row) ----------------
__global__ __launch_bounds__(256)
void ln_split_kernel(const float* __restrict__ x,
                     const float* __restrict__ gg,
                     const float* __restrict__ bb,
                     fp16* __restrict__ oh, fp16* __restrict__ ol) {
    __shared__ float rs[8], rs2[8];
    const int row = blockIdx.x, tid = threadIdx.x;
    const float4* xr = (const float4*)(x + (long)row * NC);
    float4 v = xr[tid];
    float s  = v.x + v.y + v.z + v.w;
    float s2 = v.x*v.x + v.y*v.y + v.z*v.z + v.w*v.w;
    #pragma unroll
    for (int off = 16; off > 0; off >>= 1) {
        s  += __shfl_xor_sync(0xffffffff, s,  off);
        s2 += __shfl_xor_sync(0xffffffff, s2, off);
    }
    if ((tid & 31) == 0) { rs[tid >> 5] = s; rs2[tid >> 5] = s2; }
    __syncthreads();
    if (tid < 8) {
        s = rs[tid]; s2 = rs2[tid];
        #pragma unroll
        for (int off = 4; off > 0; off >>= 1) {
            s  += __shfl_xor_sync(0xff, s,  off);
            s2 += __shfl_xor_sync(0xff, s2, off);
        }
        if (tid == 0) { rs[0] = s; rs2[0] = s2; }
    }
    __syncthreads();
    float mean = rs[0] * (1.0f / NC);
    float var  = rs2[0] * (1.0f / NC) - mean * mean;
    float rstd = rsqrtf(var + LN_EPS);
    const float4* g4 = (const float4*)gg;
    const float4* b4 = (const float4*)bb;
    float4 g = g4[tid], bv = b4[tid];
    float o0 = (v.x - mean) * rstd * g.x + bv.x;
    float o1 = (v.y - mean) * rstd * g.y + bv.y;
    float o2 = (v.z - mean) * rstd * g.z + bv.z;
    float o3 = (v.w - mean) * rstd * g.w + bv.w;
    fp16 h0,l0,h1,l1,h2,l2,h3,l3;
    split2h(o0,h0,l0); split2h(o1,h1,l1); split2h(o2,h2,l2); split2h(o3,h3,l3);
    uint32_t* oh2 = (uint32_t*)(oh + (long)row * NC);
    uint32_t* ol2 = (uint32_t*)(ol + (long)row * NC);
    oh2[tid*2]   = pack2(h0, h1);
    oh2[tid*2+1] = pack2(h2, h3);
    ol2[tid*2]   = pack2(l0, l1);
    ol2[tid*2+1] = pack2(l2, l3);
}

// ---------------- mma.sync helpers ----------------
__device__ __forceinline__ void ldsm_x4(uint32_t addr, uint32_t& r0, uint32_t& r1,
                                        uint32_t& r2, uint32_t& r3) {
    asm volatile("ldmatrix.sync.aligned.m8n8.x4.shared.b16 {%0,%1,%2,%3},[%4];"
                 : "=r"(r0), "=r"(r1), "=r"(r2), "=r"(r3) : "r"(addr));
}
__device__ __forceinline__ void ldsm_x4_t(uint32_t addr, uint32_t& r0, uint32_t& r1,
                                          uint32_t& r2, uint32_t& r3) {
    asm volatile("ldmatrix.sync.aligned.m8n8.x4.trans.shared.b16 {%0,%1,%2,%3},[%4];"
                 : "=r"(r0), "=r"(r1), "=r"(r2), "=r"(r3) : "r"(addr));
}
__device__ __forceinline__ void mma_f16(float* c, const uint32_t* a, const uint32_t* b) {
    asm volatile(
        "mma.sync.aligned.m16n8k16.row.col.f32.f16.f16.f32 "
        "{%0,%1,%2,%3},{%4,%5,%6,%7},{%8,%9},{%0,%1,%2,%3};"
        : "+f"(c[0]), "+f"(c[1]), "+f"(c[2]), "+f"(c[3])
        : "r"(a[0]), "r"(a[1]), "r"(a[2]), "r"(a[3]), "r"(b[0]), "r"(b[1]));
}
__device__ __forceinline__ void cpa16(uint32_t s, const void* g) {
    asm volatile("cp.async.cg.shared.global [%0],[%1],16;" :: "r"(s), "l"(g));
}

// ---------------- fp16 split-activation tensor-core GEMM (R7 pipeline) ----------------
// C = Ah@B + Al@B, fp32 accum. A split fp16 (err 2^-24); B single fp16 (err 2^-12).
// BM=128 BN=128 BK=32, 256 threads (8 warps 4x2), warp tile 32x64.
// stage 24KB: Ah@0 (8K) | Al@8K (8K) | B@16K (8K); 2 stages = 48K -> 2 CTAs/SM.
// EPI: 0 = fp32 out; 1 = +bias +res fp32 out; 2 = +bias relu split fp16 out.
#define SMEM_GEMM 49152
#define STG_B 24576

template<int EPI>
__global__ __launch_bounds__(256, 2)
void mma_gemm(int M, int N, int K,
              const fp16* __restrict__ Ah, const fp16* __restrict__ Al,
              const fp16* __restrict__ Bw,
              const float* __restrict__ bias, const float* __restrict__ res,
              float* __restrict__ Cf, fp16* __restrict__ Ch, fp16* __restrict__ Cl) {
    extern __shared__ char smem[];
    const uint32_t sbase0 = (uint32_t)__cvta_generic_to_shared(smem);
    const int tid  = threadIdx.x;
    const int lane = tid & 31, warp = tid >> 5;
    const int wm = warp >> 1, wn = warp & 1;        // 4 x 2 warps
    const int m0 = blockIdx.y * 128, n0 = blockIdx.x * 128;
    const int r8 = lane & 7, grp = lane >> 3;
    const int g = lane >> 2, t4 = lane & 3;

    float acc[2][8][4];
    #pragma unroll
    for (int i = 0; i < 2; i++)
        #pragma unroll
        for (int j = 0; j < 8; j++)
            #pragma unroll
            for (int r = 0; r < 4; r++) acc[i][j][r] = 0.f;

    const int T = K >> 5;

    auto load_stage = [&](int stage, int k0) {
        uint32_t sb = sbase0 + stage * STG_B;
        #pragma unroll
        for (int it = 0; it < 2; it++) {
            int c = it * 256 + tid;          // 0..511
            int r = c >> 2, cc = c & 3;      // 4 x 16B chunks per 64B row
            uint32_t so = r * 64 + ((cc ^ ((r >> 1) & 3)) << 4);
            size_t ga = (size_t)(m0 + r) * K + k0 + (cc << 3);
            cpa16(sb +        so, Ah + ga);
            cpa16(sb + 8192 + so, Al + ga);
        }
        #pragma unroll
        for (int it = 0; it < 1; it++) {
            // B: 32 k-rows x 256B, 512 chunks of 16B -> 2 chunks per thread
            int c0 = tid;                    // 0..255
            int k = c0 >> 3, nc = c0 & 7;
            uint32_t so = k * 256 + (((nc * 2) ^ (k & 7)) << 4);
            uint32_t so2 = k * 256 + ((((nc * 2 + 1)) ^ (k & 7)) << 4);
            size_t ga = (size_t)(k0 + k) * N + n0 + (nc * 2) * 8;
            cpa16(sb + 16384 + so,  Bw + ga);
            cpa16(sb + 16384 + so2, Bw + ga + 8);
        }
    };

    load_stage(0, 0);
    asm volatile("cp.async.commit_group;");

    for (int t = 0; t < T; t++) {
        if (t + 1 < T) {
            load_stage((t + 1) & 1, (t + 1) << 5);
            asm volatile("cp.async.commit_group;");
            asm volatile("cp.async.wait_group 1;");
        } else {
            asm volatile("cp.async.wait_group 0;");
        }
        __syncthreads();

        uint32_t sA  = sbase0 + (t & 1) * STG_B;
        uint32_t sAl = sA + 8192;
        uint32_t sB  = sA + 16384;

        #pragma unroll
        for (int kt = 0; kt < 2; kt++) {
            uint32_t ah[2][4], al_[2][4];
            #pragma unroll
            for (int i = 0; i < 2; i++) {
                int row = wm * 32 + i * 16 + r8 + ((grp & 1) << 3);
                int kc  = kt * 2 + (grp >> 1);
                uint32_t off = row * 64 + ((kc ^ ((row >> 1) & 3)) << 4);
                ldsm_x4(sA  + off, ah[i][0],  ah[i][1],  ah[i][2],  ah[i][3]);
                ldsm_x4(sAl + off, al_[i][0], al_[i][1], al_[i][2], al_[i][3]);
            }
            #pragma unroll
            for (int half = 0; half < 2; half++) {
                uint32_t bf[4][2];
                #pragma unroll
                for (int j4 = 0; j4 < 2; j4++) {
                    int k = kt * 16 + r8 + ((grp & 1) << 3);
                    int nch = wn * 8 + (half * 2 + j4) * 2 + (grp >> 1);
                    uint32_t off = k * 256 + ((nch ^ (k & 7)) << 4);
                    ldsm_x4_t(sB + off, bf[2*j4][0], bf[2*j4][1], bf[2*j4+1][0], bf[2*j4+1][1]);
                }
                #pragma unroll
                for (int i = 0; i < 2; i++)
                    #pragma unroll
                    for (int jl = 0; jl < 4; jl++) {
                        float* a = acc[i][half * 4 + jl];
                        mma_f16(a, ah[i],  bf[jl]);
                        mma_f16(a, al_[i], bf[jl]);
                    }
            }
        }
        __syncthreads();
    }

    #pragma unroll
    for (int i = 0; i < 2; i++) {
        int ra = m0 + wm * 32 + i * 16 + g;
        int rb = ra + 8;
        #pragma unroll
        for (int j = 0; j < 8; j++) {
            int c = n0 + wn * 64 + j * 8 + t4 * 2;
            float v0 = acc[i][j][0], v1 = acc[i][j][1];
            float v2 = acc[i][j][2], v3 = acc[i][j][3];
            if (EPI >= 1) {
                float b0 = bias[c], b1 = bias[c + 1];
                v0 += b0; v1 += b1; v2 += b0; v3 += b1;
            }
            if (EPI == 1) {
                const float2 ra2 = *(const float2*)(res + (size_t)ra * N + c);
                const float2 rb2 = *(const float2*)(res + (size_t)rb * N + c);
                v0 += ra2.x; v1 += ra2.y; v2 += rb2.x; v3 += rb2.y;
            }
            if (EPI <= 1) {
                *(float2*)(Cf + (size_t)ra * N + c) = make_float2(v0, v1);
                *(float2*)(Cf + (size_t)rb * N + c) = make_float2(v2, v3);
            } else {
                v0 = fmaxf(v0, 0.f); v1 = fmaxf(v1, 0.f);
                v2 = fmaxf(v2, 0.f); v3 = fmaxf(v3, 0.f);
                fp16 h0,l0,h1,l1,h2,l2,h3,l3;
                split2h(v0,h0,l0); split2h(v1,h1,l1);
                split2h(v2,h2,l2); split2h(v3,h3,l3);
                *(uint32_t*)(Ch + (size_t)ra * N + c) = pack2(h0, h1);
                *(uint32_t*)(Ch + (size_t)rb * N + c) = pack2(h2, h3);
                *(uint32_t*)(Cl + (size_t)ra * N + c) = pack2(l0, l1);
                *(uint32_t*)(Cl + (size_t)rb * N + c) = pack2(l2, l3);
            }
        }
    }
}

// ---------------- flash attention (fp32 compute, split-fp16 output) ----------------
#define AQ_PAD 65
#define AV_PAD 68
#define A_QS 0
#define A_KS (64*AQ_PAD)
#define A_VS (A_KS + 64*AQ_PAD)
#define A_PS (A_VS + 64*AV_PAD)
#define A_ST (A_PS + 64*AQ_PAD)
#define SMEM_ATTN ((A_ST + 3*64) * 4)

__global__ __launch_bounds__(256, 2)
void attn_kernel(const float* __restrict__ QKV,
                 fp16* __restrict__ Yh, fp16* __restrict__ Yl) {
    extern __shared__ float sm[];
    float* Qs = sm + A_QS;          // [d][q]
    float* Ks = sm + A_KS;          // [d][s]
    float* Vs = sm + A_VS;          // [s][d]
    float* Ps = sm + A_PS;          // [q][s]
    float* smM = sm + A_ST;
    float* smL = smM + 64;
    float* smC = smL + 64;

    const int qt = (int)(gridDim.x - 1 - blockIdx.x);   // heavy tiles first
    const int h = blockIdx.y, b = blockIdx.z;
    const int tid = threadIdx.x;
    const int qx = tid >> 4, kx = tid & 15;
    const long baseQ = (long)(b * NT) * C3 + h * HDIM;
    const long baseK = baseQ + NC;
    const long baseV = baseQ + 2 * NC;
    const int q0 = qt * 64;

    #pragma unroll
    for (int it = 0; it < 4; it++) {
        int i = it * 256 + tid;
        int r = i >> 4, dc = (i & 15) * 4;
        float4 v = *(const float4*)&QKV[baseQ + (long)(q0 + r) * C3 + dc];
        Qs[(dc+0)*AQ_PAD + r] = v.x; Qs[(dc+1)*AQ_PAD + r] = v.y;
        Qs[(dc+2)*AQ_PAD + r] = v.z; Qs[(dc+3)*AQ_PAD + r] = v.w;
    }
    if (tid < 64) { smM[tid] = -1e30f; smL[tid] = 0.f; }

    float O[4][4];
    #pragma unroll
    for (int i = 0; i < 4; i++)
        #pragma unroll
        for (int j = 0; j < 4; j++) O[i][j] = 0.f;
    __syncthreads();

    for (int jt = 0; jt <= qt; jt++) {
        #pragma unroll
        for (int it = 0; it < 4; it++) {
            int i = it * 256 + tid;
            int r = i >> 4, dc = (i & 15) * 4;
            float4 v = *(const float4*)&QKV[baseK + (long)(jt * 64 + r) * C3 + dc];
            Ks[(dc+0)*AQ_PAD + r] = v.x; Ks[(dc+1)*AQ_PAD + r] = v.y;
            Ks[(dc+2)*AQ_PAD + r] = v.z; Ks[(dc+3)*AQ_PAD + r] = v.w;
            float4 w = *(const float4*)&QKV[baseV + (long)(jt * 64 + r) * C3 + dc];
            *(float4*)&Vs[r * AV_PAD + dc] = w;
        }
        __syncthreads();

        float S[4][4];
        #pragma unroll
        for (int i = 0; i < 4; i++)
            #pragma unroll
            for (int j = 0; j < 4; j++) S[i][j] = 0.f;
        #pragma unroll 4
        for (int d = 0; d < 64; d++) {
            float qm[4], kn[4];
            #pragma unroll
            for (int i = 0; i < 4; i++) qm[i] = Qs[d*AQ_PAD + qx*4 + i];
            #pragma unroll
            for (int j = 0; j < 4; j++) kn[j] = Ks[d*AQ_PAD + kx*4 + j];
            #pragma unroll
            for (int i = 0; i < 4; i++)
                #pragma unroll
                for (int j = 0; j < 4; j++) S[i][j] += qm[i] * kn[j];
        }
        const bool diag = (jt == qt);
        #pragma unroll
        for (int i = 0; i < 4; i++)
            #pragma unroll
            for (int j = 0; j < 4; j++) {
                float s = S[i][j] * 0.125f;
                if (diag && (jt*64 + kx*4 + j > q0 + qx*4 + i)) s = -1e30f;
                Ps[(qx*4+i)*AQ_PAD + kx*4 + j] = s;
            }
        __syncthreads();

        if (tid < 64) {
            float mo = smM[tid], rmax = mo;
            #pragma unroll 8
            for (int s = 0; s < 64; s++) rmax = fmaxf(rmax, Ps[tid*AQ_PAD + s]);
            float c = __expf(mo - rmax);
            float rsum = 0.f;
            #pragma unroll 8
            for (int s = 0; s < 64; s++) {
                float p = __expf(Ps[tid*AQ_PAD + s] - rmax);
                Ps[tid*AQ_PAD + s] = p;
                rsum += p;
            }
            smL[tid] = smL[tid] * c + rsum;
            smM[tid] = rmax;
            smC[tid] = c;
        }
        __syncthreads();

        float cq[4];
        #pragma unroll
        for (int i = 0; i < 4; i++) cq[i] = smC[qx*4 + i];
        #pragma unroll
        for (int i = 0; i < 4; i++)
            #pragma unroll
            for (int j = 0; j < 4; j++) O[i][j] *= cq[i];
        #pragma unroll 4
        for (int s = 0; s < 64; s++) {
            float pv[4], vv[4];
            #pragma unroll
            for (int i = 0; i < 4; i++) pv[i] = Ps[(qx*4+i)*AQ_PAD + s];
            #pragma unroll
            for (int j = 0; j < 4; j++) vv[j] = Vs[s*AV_PAD + kx*4 + j];
            #pragma unroll
            for (int i = 0; i < 4; i++)
                #pragma unroll
                for (int j = 0; j < 4; j++) O[i][j] += pv[i] * vv[j];
        }
        __syncthreads();
    }

    #pragma unroll
    for (int i = 0; i < 4; i++) {
        float inv = 1.0f / smL[qx*4 + i];
        long row = (long)(b * NT + q0 + qx*4 + i);
        long o = row * NC + h * HDIM + kx*4;
        #pragma unroll
        for (int j = 0; j < 4; j += 2) {
            float v0 = O[i][j] * inv, v1 = O[i][j+1] * inv;
            fp16 h0, l0, h1, l1;
            split2h(v0, h0, l0); split2h(v1, h1, l1);
            *(uint32_t*)(Yh + o + j) = pack2(h0, h1);
            *(uint32_t*)(Yl + o + j) = pack2(l0, l1);
        }
    }
}

// ---------------- host driver ----------------
extern "C" void kernel_launch(void* const* d_in, const int* in_sizes, int n_in,
                              void* d_out, int out_size) {
    const int*   idx  = (const int*)  d_in[0];
    const float* tok  = (const float*)d_in[1];
    const float* pos  = (const float*)d_in[2];
    const float* wq   = (const float*)d_in[3];
    const float* wk   = (const float*)d_in[4];
    const float* wv   = (const float*)d_in[5];
    const float* wo   = (const float*)d_in[6];
    const float* bo   = (const float*)d_in[7];
    const float* ln1g = (const float*)d_in[8];
    const float* ln1b = (const float*)d_in[9];
    const float* ln2g = (const float*)d_in[10];
    const float* ln2b = (const float*)d_in[11];
    const float* w1   = (const float*)d_in[12];
    const float* b1   = (const float*)d_in[13];
    const float* w2   = (const float*)d_in[14];
    const float* b2   = (const float*)d_in[15];
    const float* lnfg = (const float*)d_in[16];
    const float* lnfb = (const float*)d_in[17];
    const float* wlm  = (const float*)d_in[18];
    float* out = (float*)d_out;

    static bool attr_done = false;
    if (!attr_done) {
        cudaFuncSetAttribute(mma_gemm<0>, cudaFuncAttributeMaxDynamicSharedMemorySize, SMEM_GEMM);
        cudaFuncSetAttribute(mma_gemm<1>, cudaFuncAttributeMaxDynamicSharedMemorySize, SMEM_GEMM);
        cudaFuncSetAttribute(mma_gemm<2>, cudaFuncAttributeMaxDynamicSharedMemorySize, SMEM_GEMM);
        cudaFuncSetAttribute(attn_kernel, cudaFuncAttributeMaxDynamicSharedMemorySize, SMEM_ATTN);
        attr_done = true;
    }

    float *x, *qkv;
    fp16 *xnh, *xnl, *yh, *yl, *hh, *hl;
    fp16 *wqkvp, *wop, *w1p, *w2p, *lmp;
    cudaGetSymbolAddress((void**)&x,     g_x);
    cudaGetSymbolAddress((void**)&qkv,   g_qkv);
    cudaGetSymbolAddress((void**)&xnh,   g_xn_h);
    cudaGetSymbolAddress((void**)&xnl,   g_xn_l);
    cudaGetSymbolAddress((void**)&yh,    g_y_h);
    cudaGetSymbolAddress((void**)&yl,    g_y_l);
    cudaGetSymbolAddress((void**)&hh,    g_h_h);
    cudaGetSymbolAddress((void**)&hl,    g_h_l);
    cudaGetSymbolAddress((void**)&wqkvp, g_wqkv);
    cudaGetSymbolAddress((void**)&wop,   g_wo);
    cudaGetSymbolAddress((void**)&w1p,   g_w1);
    cudaGetSymbolAddress((void**)&w2p,   g_w2);
    cudaGetSymbolAddress((void**)&lmp,   g_lm);

    pack_qkv_kernel<<<4096, 256>>>(wq, wk, wv, wqkvp, (long)NL*NC*C3);
    conv4_kernel<<<8192, 256>>>(wo,  wop, (long)NL*NC*NC,
                                w1,  w1p, (long)NL*NC*NF,
                                w2,  w2p, (long)NL*NF*NC,
                                wlm, lmp, (long)NC*NV);
    embed_kernel<<<MROWS, 256>>>(idx, tok, pos);

    for (int l = 0; l < NL; l++) {
        const long oQ = (long)l * NC * C3;
        const long oO = (long)l * NC * NC;
        const long o1 = (long)l * NC * NF;
        const long o2 = (long)l * NF * NC;

        ln_split_kernel<<<MROWS, 256>>>(x, ln1g + l*NC, ln1b + l*NC, xnh, xnl);
        mma_gemm<0><<<dim3(C3/128, MROWS/128), 256, SMEM_GEMM>>>(
            MROWS, C3, NC, xnh, xnl, wqkvp + oQ,
            nullptr, nullptr, qkv, nullptr, nullptr);
        attn_kernel<<<dim3(NT/64, NH, NB), 256, SMEM_ATTN>>>(qkv, yh, yl);
        mma_gemm<1><<<dim3(NC/128, MROWS/128), 256, SMEM_GEMM>>>(
            MROWS, NC, NC, yh, yl, wop + oO,
            bo + l*NC, x, x, nullptr, nullptr);
        ln_split_kernel<<<MROWS, 256>>>(x, ln2g + l*NC, ln2b + l*NC, xnh, xnl);
        mma_gemm<2><<<dim3(NF/128, MROWS/128), 256, SMEM_GEMM>>>(
            MROWS, NF, NC, xnh, xnl, w1p + o1,
            b1 + l*NF, nullptr, nullptr, hh, hl);
        mma_gemm<1><<<dim3(NC/128, MROWS/128), 256, SMEM_GEMM>>>(
            MROWS, NC, NF, hh, hl, w2p + o2,
            b2 + l*NC, x, x, nullptr, nullptr);
    }

    ln_split_kernel<<<MROWS, 256>>>(x, lnfg, lnfb, xnh, xnl);
    mma_gemm<0><<<dim3(NV/128, MROWS/128), 256, SMEM_GEMM>>>(
        MROWS, NV, NC, xnh, xnl, lmp,
        nullptr, nullptr, out, nullptr, nullptr);
}